// round 4
// baseline (speedup 1.0000x reference)
#include <cuda_runtime.h>

// Problem constants (B=8192, L=2048, T=1024)
#define NB 8192
#define NT 1024
#define THREADS 256
#define NWARPS (THREADS / 32)

__device__ double g_sum = 0.0;          // zeroed by last block each launch
__device__ unsigned int g_count = 0;    // zeroed by last block each launch

// Thread t owns two 2-point chunks of its row:
//   chunk A = pred float4[t]      -> points 2t,   2t+1     (first half)
//   chunk B = pred float4[256+t]  -> points 512+2t, 513+2t (second half)
// Every global load is unit-stride across the warp (perfectly coalesced).
__global__ __launch_bounds__(THREADS) void traj_loss_fused(
    const float* __restrict__ pred,
    const float* __restrict__ pos_true,
    float* __restrict__ out)
{
    const int b    = blockIdx.x;
    const int tid  = threadIdx.x;
    const int lane = tid & 31;
    const int warp = tid >> 5;

    const float4* pv = (const float4*)(pred + (size_t)b * (2 * NT));
    float4 a = pv[tid];            // points 2t, 2t+1        (x,y,x,y)
    float4 c = pv[THREADS + tid];  // points 512+2t, 513+2t

    const float* tp = pos_true + (size_t)b * (2 * NT);
    const float2* txp = (const float2*)tp;         // true x, 512 float2s
    const float2* typ = (const float2*)(tp + NT);  // true y
    float2 txA = txp[tid], txB = txp[THREADS + tid];
    float2 tyA = typ[tid], tyB = typ[THREADS + tid];

    // per-chunk delta sums
    float ax = a.x + a.z, ay = a.y + a.w;   // chunk A
    float bx = c.x + c.z, by = c.y + c.w;   // chunk B

    // --- warp inclusive scan of (ax, ay, bx, by) ---
    float sax = ax, say = ay, sbx = bx, sby = by;
    #pragma unroll
    for (int d = 1; d < 32; d <<= 1) {
        float u0 = __shfl_up_sync(0xffffffffu, sax, d);
        float u1 = __shfl_up_sync(0xffffffffu, say, d);
        float u2 = __shfl_up_sync(0xffffffffu, sbx, d);
        float u3 = __shfl_up_sync(0xffffffffu, sby, d);
        if (lane >= d) { sax += u0; say += u1; sbx += u2; sby += u3; }
    }

    __shared__ float wAx[NWARPS], wAy[NWARPS], wBx[NWARPS], wBy[NWARPS];
    if (lane == 31) { wAx[warp] = sax; wAy[warp] = say; wBx[warp] = sbx; wBy[warp] = sby; }
    __syncthreads();

    // exclusive offsets; chunk B additionally gets the full first-half total
    float oAx = sax - ax, oAy = say - ay;
    float oBx = sbx - bx, oBy = sby - by;
    float totAx = 0.0f, totAy = 0.0f;
    #pragma unroll
    for (int w = 0; w < NWARPS; w++) {
        float vx = wAx[w], vy = wAy[w], ux = wBx[w], uy = wBy[w];
        totAx += vx; totAy += vy;
        if (w < warp) { oAx += vx; oAy += vy; oBx += ux; oBy += uy; }
    }
    oBx += totAx; oBy += totAy;

    // --- cumsum + squared error ---
    float err = 0.0f, cx, cy, ex, ey;
    // chunk A: points 2t, 2t+1
    cx = oAx + a.x; cy = oAy + a.y; ex = cx - txA.x; ey = cy - tyA.x; err += ex * ex + ey * ey;
    cx += a.z;      cy += a.w;      ex = cx - txA.y; ey = cy - tyA.y; err += ex * ex + ey * ey;
    // chunk B: points 512+2t, 513+2t
    cx = oBx + c.x; cy = oBy + c.y; ex = cx - txB.x; ey = cy - tyB.x; err += ex * ex + ey * ey;
    cx += c.z;      cy += c.w;      ex = cx - txB.y; ey = cy - tyB.y; err += ex * ex + ey * ey;

    // --- block reduce in double ---
    double e = (double)err;
    #pragma unroll
    for (int d = 16; d > 0; d >>= 1)
        e += __shfl_down_sync(0xffffffffu, e, d);

    __shared__ double wsum[NWARPS];
    if (lane == 0) wsum[warp] = e;
    __syncthreads();

    if (warp == 0) {
        double v = (lane < NWARPS) ? wsum[lane] : 0.0;
        #pragma unroll
        for (int d = 4; d > 0; d >>= 1)
            v += __shfl_down_sync(0xffffffffu, v, d);

        if (lane == 0) {
            atomicAdd(&g_sum, v);
            __threadfence();
            unsigned int old = atomicAdd(&g_count, 1u);
            if (old == NB - 1) {
                // last block: read-and-zero accumulator, reset counter (graph-replay safe)
                unsigned long long bits =
                    atomicExch((unsigned long long*)&g_sum, 0ULL);
                g_count = 0;
                out[0] = (float)__longlong_as_double(bits);
            }
        }
    }
}

extern "C" void kernel_launch(void* const* d_in, const int* in_sizes, int n_in,
                              void* d_out, int out_size)
{
    const float* pred     = (const float*)d_in[0];  // traj_pred
    // d_in[1] = traj_du_true — unused by the reference; never read.
    const float* pos_true = (const float*)d_in[2];  // traj_pos_true

    traj_loss_fused<<<NB, THREADS>>>(pred, pos_true, (float*)d_out);
}